// round 12
// baseline (speedup 1.0000x reference)
#include <cuda_runtime.h>

// ---------------------------------------------------------------------------
// Photonic Clements mesh, N=128, with SERIAL-DEPTH HALVING.
//   out = OutStage . L254 ... L0 . InStage(x)  is split at an X boundary:
//     Chain A (128 cols):  layers 0..126 on the real input  -> state 256x128
//     Chain B (256 cols):  layers 127..254 + OutStage on identity -> B 128x256
//   run CONCURRENTLY in one 384-block kernel, then out = B @ A_state
//   (33 MFLOP complex matmul).
// Per-warp structure = proven round-10/11 kernel (shfl hoist, 3-slot rotation,
// predicate-free corners, pointer-strided loads, L1 prefetch).
// Output serialization identical to rounds 4-11 (mode on out_size).
// ---------------------------------------------------------------------------

#define NCOLS   128
#define NLAYERS 255
#define FULL    0xffffffffu

#define AM_  0.97467943448089633f    // sqrt(1-0.05)
#define PP_  0.71063352017759484f    // sqrt(0.5+0.005)
#define QQ_  0.70356236397351441f    // sqrt(0.5-0.005)
#define AMP_ (AM_*PP_)
#define AMQ_ (AM_*QQ_)
#define AX_  0.98994949366116653f    // sqrt(1-0.02)
#define XC_  (AX_*0.1f)                       // aX*sqrt(CT)
#define XS_  (AX_*0.99498743710661995f)       // aX*sqrt(1-CT), corner scalar

// phase table: layer k, lane t reads float4s [k*64+2t], [k*64+2t+1].
// +1024 float4 (16 KB) pad: B-chain trailing reloads/prefetches stay in-bounds.
__device__ float4 g_phase4[NLAYERS * 64 + 1024];
// intermediates: A state (gA[row*128+col]) and B transposed (gBT[e*128+row])
__device__ float2 g_A [256 * NCOLS];
__device__ float2 g_BT[256 * NCOLS];

__global__ void phase_kernel(const float* __restrict__ theta_even) {
    int i = blockIdx.x * blockDim.x + threadIdx.x;
    if (i < NLAYERS * NCOLS) {
        float s, c;
        __sincosf(theta_even[i], &s, &c);   // fast path; inputs in [0, 2pi)
        reinterpret_cast<float2*>(g_phase4)[i] = make_float2(c, s);
    }
}

#define CMUL(v, c_, s_) do { \
    float _nx = fmaf((v).x, (c_), -(v).y * (s_)); \
    float _ny = fmaf((v).x, (s_),  (v).y * (c_)); \
    (v).x = _nx; (v).y = _ny; } while (0)

#define MIX(a, b, A, B) do { \
    float _ar = fmaf((A), (a).x, -(B) * (b).y); \
    float _ai = fmaf((A), (a).y,  (B) * (b).x); \
    float _br = fmaf((A), (b).x, -(B) * (a).y); \
    float _bi = fmaf((A), (b).y,  (B) * (a).x); \
    (a).x = _ar; (a).y = _ai; (b).x = _br; (b).y = _bi; } while (0)

#define PF(p) do { \
    asm volatile("prefetch.global.L1 [%0];"      :: "l"(p)); \
    asm volatile("prefetch.global.L1 [%0+1024];" :: "l"(p)); } while (0)

// One iteration: D(a), M, D(b), M, X. Boundary pairs first; shuffles overlap
// the middle-pair math. Corners folded into per-lane coeffs cA/cB.
#define ITER(A0, A1, B0, B1) do { \
    CMUL(v0, (A0).x, (A0).y); \
    CMUL(v6, (A1).z, (A1).w); \
    MIX(v0, v1, AMP_, AMQ_); \
    MIX(v6, v7, AMP_, AMQ_); \
    CMUL(v0, (B0).x, (B0).y); \
    CMUL(v6, (B1).z, (B1).w); \
    MIX(v0, v1, AMP_, AMQ_); \
    MIX(v6, v7, AMP_, AMQ_); \
    float _nb0x = __shfl_down_sync(FULL, v0.x, 1); \
    float _nb0y = __shfl_down_sync(FULL, v0.y, 1); \
    float _nb7x = __shfl_up_sync  (FULL, v7.x, 1); \
    float _nb7y = __shfl_up_sync  (FULL, v7.y, 1); \
    CMUL(v2, (A0).z, (A0).w); \
    CMUL(v4, (A1).x, (A1).y); \
    MIX(v2, v3, AMP_, AMQ_); \
    MIX(v4, v5, AMP_, AMQ_); \
    CMUL(v2, (B0).z, (B0).w); \
    CMUL(v4, (B1).x, (B1).y); \
    MIX(v2, v3, AMP_, AMQ_); \
    MIX(v4, v5, AMP_, AMQ_); \
    MIX(v1, v2, XC_, XS_); \
    MIX(v3, v4, XC_, XS_); \
    MIX(v5, v6, XC_, XS_); \
    float _n7x = fmaf(cA7, v7.x, -cB7 * _nb0y); \
    float _n7y = fmaf(cA7, v7.y,  cB7 * _nb0x); \
    float _n0x = fmaf(cA0, v0.x, -cB0 * _nb7y); \
    float _n0y = fmaf(cA0, v0.y,  cB0 * _nb7x); \
    v7.x = _n7x; v7.y = _n7y; \
    v0.x = _n0x; v0.y = _n0y; } while (0)

#define LDP(S0, S1, S2, S3, p) do { \
    (S0) = (p)[0]; (S1) = (p)[1]; (S2) = (p)[64]; (S3) = (p)[65]; } while (0)

// 21 unroll-3 trips = 63 iterations; each slot reloads j+3 right after use.
#define RUN63() \
    _Pragma("unroll 1") \
    for (int m = 0; m < 21; m++) { \
        ITER(s0a0, s0a1, s0b0, s0b1); \
        LDP(s0a0, s0a1, s0b0, s0b1, p0); \
        p0 += 384; PF(p0); \
        ITER(s1a0, s1a1, s1b0, s1b1); \
        LDP(s1a0, s1a1, s1b0, s1b1, p1); \
        p1 += 384; PF(p1); \
        ITER(s2a0, s2a1, s2b0, s2b1); \
        LDP(s2a0, s2a1, s2b0, s2b1, p2); \
        p2 += 384; PF(p2); \
    }

__global__ void __launch_bounds__(32, 3)
chains_kernel(const float* __restrict__ theta_in,
              const float* __restrict__ theta_out)
{
    const int bid = blockIdx.x;
    const int t   = threadIdx.x;   // lane: rows 8t..8t+7

    const float cA7 = (t < 31) ? XC_ : XS_;
    const float cB7 = (t < 31) ? XS_ : 0.f;
    const float cA0 = (t > 0)  ? XC_ : XS_;
    const float cB0 = (t > 0)  ? XS_ : 0.f;

    float2 v0 = {0.f, 0.f}, v1 = {0.f, 0.f}, v2 = {0.f, 0.f}, v3 = {0.f, 0.f};
    float2 v4 = {0.f, 0.f}, v5 = {0.f, 0.f}, v6 = {0.f, 0.f}, v7 = {0.f, 0.f};

    const float4* base = g_phase4 + 2 * t;
    float4 s0a0, s0a1, s0b0, s0b1;
    float4 s1a0, s1a1, s1b0, s1b1;
    float4 s2a0, s2a1, s2b0, s2b1;

    if (bid < NCOLS) {
        // ===== CHAIN A: input column c through layers 0..126 =====
        const int c = bid;
        {
            float s, co;
            sincosf(theta_in[c], &s, &co);
            float2 ain = make_float2( AMP_ * co, AMP_ * s);
            float2 bin = make_float2(-AMQ_ * s,  AMQ_ * co);
            int slot = 2 * c - 8 * t;
            if      (slot == 0) { v0 = ain; v1 = bin; }
            else if (slot == 2) { v2 = ain; v3 = bin; }
            else if (slot == 4) { v4 = ain; v5 = bin; }
            else if (slot == 6) { v6 = ain; v7 = bin; }
        }
        // D0, M, X (hoisted form)
        {
            float4 p01 = base[0], p23 = base[1];
            CMUL(v0, p01.x, p01.y);
            CMUL(v6, p23.z, p23.w);
            MIX(v0, v1, AMP_, AMQ_);
            MIX(v6, v7, AMP_, AMQ_);
            float nb0x = __shfl_down_sync(FULL, v0.x, 1);
            float nb0y = __shfl_down_sync(FULL, v0.y, 1);
            float nb7x = __shfl_up_sync  (FULL, v7.x, 1);
            float nb7y = __shfl_up_sync  (FULL, v7.y, 1);
            CMUL(v2, p01.z, p01.w);
            CMUL(v4, p23.x, p23.y);
            MIX(v2, v3, AMP_, AMQ_);
            MIX(v4, v5, AMP_, AMQ_);
            MIX(v1, v2, XC_, XS_);
            MIX(v3, v4, XC_, XS_);
            MIX(v5, v6, XC_, XS_);
            float n7x = fmaf(cA7, v7.x, -cB7 * nb0y);
            float n7y = fmaf(cA7, v7.y,  cB7 * nb0x);
            float n0x = fmaf(cA0, v0.x, -cB0 * nb7y);
            float n0y = fmaf(cA0, v0.y,  cB0 * nb7x);
            v7.x = n7x; v7.y = n7y;
            v0.x = n0x; v0.y = n0y;
        }
        // iterations j=0..62 (layers 1..126)
        LDP(s0a0, s0a1, s0b0, s0b1, base + 1 * 64);
        LDP(s1a0, s1a1, s1b0, s1b1, base + 3 * 64);
        LDP(s2a0, s2a1, s2b0, s2b1, base + 5 * 64);
        const float4* p0 = base + 7 * 64;
        const float4* p1 = base + 9 * 64;
        const float4* p2 = base + 11 * 64;
        PF(p0); PF(p1); PF(p2);
        RUN63();
        // store state (rows 8t..8t+7 of column c)
        g_A[(8 * t + 0) * NCOLS + c] = v0;
        g_A[(8 * t + 1) * NCOLS + c] = v1;
        g_A[(8 * t + 2) * NCOLS + c] = v2;
        g_A[(8 * t + 3) * NCOLS + c] = v3;
        g_A[(8 * t + 4) * NCOLS + c] = v4;
        g_A[(8 * t + 5) * NCOLS + c] = v5;
        g_A[(8 * t + 6) * NCOLS + c] = v6;
        g_A[(8 * t + 7) * NCOLS + c] = v7;
    } else {
        // ===== CHAIN B: identity column e through layers 127..254 + OutStage =====
        const int e = bid - NCOLS;   // 0..255
        {
            int rel = e - 8 * t;
            if (rel == 0) v0.x = 1.f;
            if (rel == 1) v1.x = 1.f;
            if (rel == 2) v2.x = 1.f;
            if (rel == 3) v3.x = 1.f;
            if (rel == 4) v4.x = 1.f;
            if (rel == 5) v5.x = 1.f;
            if (rel == 6) v6.x = 1.f;
            if (rel == 7) v7.x = 1.f;
        }
        // iterations j=63..125 (layers 127..252 + X each)
        LDP(s0a0, s0a1, s0b0, s0b1, base + 127 * 64);   // layers 127,128
        LDP(s1a0, s1a1, s1b0, s1b1, base + 129 * 64);   // layers 129,130
        LDP(s2a0, s2a1, s2b0, s2b1, base + 131 * 64);   // layers 131,132
        const float4* p0 = base + 133 * 64;   // j=66
        const float4* p1 = base + 135 * 64;   // j=67
        const float4* p2 = base + 137 * 64;   // j=68
        PF(p0); PF(p1); PF(p2);
        RUN63();
        // tail: D253, M, D254 (slot0 last reloaded j=126 -> layers 253,254)
        CMUL(v0, s0a0.x, s0a0.y);
        CMUL(v2, s0a0.z, s0a0.w);
        CMUL(v4, s0a1.x, s0a1.y);
        CMUL(v6, s0a1.z, s0a1.w);
        MIX(v0, v1, AMP_, AMQ_);
        MIX(v2, v3, AMP_, AMQ_);
        MIX(v4, v5, AMP_, AMQ_);
        MIX(v6, v7, AMP_, AMQ_);
        CMUL(v0, s0b0.x, s0b0.y);
        CMUL(v2, s0b0.z, s0b0.w);
        CMUL(v4, s0b1.x, s0b1.y);
        CMUL(v6, s0b1.z, s0b1.w);
        // OutStage rows 4t..4t+3 of B column e -> gBT[e*128 + r]
#define OUTB(va, vb, jj) do { \
            float _ox = fmaf(AMP_, (va).x, -AMQ_ * (vb).y); \
            float _oy = fmaf(AMP_, (va).y,  AMQ_ * (vb).x); \
            float _so, _co; sincosf(theta_out[jj], &_so, &_co); \
            g_BT[e * NCOLS + (jj)] = \
                make_float2(_ox * _co - _oy * _so, _ox * _so + _oy * _co); } while (0)
        OUTB(v0, v1, 4 * t);
        OUTB(v2, v3, 4 * t + 1);
        OUTB(v4, v5, 4 * t + 2);
        OUTB(v6, v7, 4 * t + 3);
#undef OUTB
    }
}

// out[r][c] = sum_e B[r][e] * A[e][c];  B[r][e] = gBT[e*128+r]
__global__ void __launch_bounds__(128, 1)
combine_kernel(float* __restrict__ out, int mode)
{
    __shared__ float2 sA[256];
    const int c = blockIdx.x;    // output column
    const int r = threadIdx.x;   // output row

    sA[r]       = g_A[r * NCOLS + c];
    sA[r + 128] = g_A[(r + 128) * NCOLS + c];
    __syncthreads();

    float ax = 0.f, ay = 0.f;
    const float2* bp = g_BT + r;
#pragma unroll 8
    for (int e = 0; e < 256; e++) {
        float2 b = bp[e * NCOLS];
        float2 a = sA[e];
        ax = fmaf(b.x, a.x, fmaf(-b.y, a.y, ax));
        ay = fmaf(b.x, a.y, fmaf( b.y, a.x, ay));
    }

    if (mode == 1) {
        out[r * NCOLS + c] = ax;                         // real part only
    } else {
        out[r * NCOLS + c]                 = ax;         // real plane
        out[NCOLS * NCOLS + r * NCOLS + c] = ay;         // imag plane
    }
}

extern "C" void kernel_launch(void* const* d_in, const int* in_sizes, int n_in,
                              void* d_out, int out_size) {
    // Inputs identified by SIZE (theta_even = unique 32640-elem array;
    // theta_in precedes theta_out).
    const float* th_ev  = nullptr;
    const float* small_[2] = {nullptr, nullptr};
    int ns = 0;
    for (int i = 0; i < n_in && i < 3; i++) {
        if (in_sizes[i] > 1000) th_ev = (const float*)d_in[i];
        else if (ns < 2)        small_[ns++] = (const float*)d_in[i];
    }
    const float* th_in  = small_[0];
    const float* th_out = small_[1];

    int mode = (out_size == NCOLS * NCOLS) ? 1 : 2;  // 16384 -> real-only, else planar

    phase_kernel<<<(NLAYERS * NCOLS + 255) / 256, 256>>>(th_ev);
    chains_kernel<<<NCOLS + 256, 32>>>(th_in, th_out);
    combine_kernel<<<NCOLS, 128>>>((float*)d_out, mode);
}